// round 2
// baseline (speedup 1.0000x reference)
#include <cuda_runtime.h>
#include <cuda_bf16.h>
#include <cstdint>

// Problem constants (from reference setup_inputs): N=50000, E=600000, D=128, NF=3, V=8
#define D_DIM 128
#define NF_DIM 3
#define V_DIM 8
#define MAX_N 50048
#define MAX_E 600064

// Scratch (device globals; no allocation allowed)
__device__ float g_h[MAX_N * D_DIM];      // normalized hidden: (nfeat + neigh) / deg
__device__ int   g_cnt[MAX_N];            // in-degree histogram
__device__ int   g_start[MAX_N + 1];      // CSR row starts
__device__ int   g_cursor[MAX_N];         // fill cursors
__device__ int   g_eid[MAX_E];            // CSR edge ids (sorted by dst)

__device__ __forceinline__ float4 f4add(float4 a, float4 b) {
    return make_float4(a.x + b.x, a.y + b.y, a.z + b.z, a.w + b.w);
}

// ---------------------------------------------------------------------------
// K0: zero histogram counters
// ---------------------------------------------------------------------------
__global__ void zero_cnt_kernel(int N) {
    int i = blockIdx.x * blockDim.x + threadIdx.x;
    if (i < N) g_cnt[i] = 0;
}

// ---------------------------------------------------------------------------
// K1: histogram of dst
// ---------------------------------------------------------------------------
__global__ void hist_kernel(const int* __restrict__ dst, int E) {
    for (int e = blockIdx.x * blockDim.x + threadIdx.x; e < E;
         e += gridDim.x * blockDim.x) {
        atomicAdd(&g_cnt[__ldg(dst + e)], 1);
    }
}

// ---------------------------------------------------------------------------
// K2: single-block exclusive scan over g_cnt -> g_start, g_cursor
// ---------------------------------------------------------------------------
__global__ void scan_kernel(int N, int E) {
    __shared__ int ssum[1024];
    int t = threadIdx.x;
    int nt = blockDim.x;
    int chunk = (N + nt - 1) / nt;
    int lo = t * chunk;
    int hi = min(lo + chunk, N);

    int s = 0;
    for (int i = lo; i < hi; i++) s += g_cnt[i];
    ssum[t] = s;
    __syncthreads();

    // Hillis-Steele inclusive scan over ssum
    for (int off = 1; off < nt; off <<= 1) {
        int v = (t >= off) ? ssum[t - off] : 0;
        __syncthreads();
        ssum[t] += v;
        __syncthreads();
    }

    int run = (t == 0) ? 0 : ssum[t - 1];  // exclusive base for this chunk
    for (int i = lo; i < hi; i++) {
        g_start[i] = run;
        g_cursor[i] = run;
        run += g_cnt[i];
    }
    if (t == 0) g_start[N] = E;
}

// ---------------------------------------------------------------------------
// K3: scatter edge ids into CSR buckets
// ---------------------------------------------------------------------------
__global__ void fill_kernel(const int* __restrict__ dst, int E) {
    for (int e = blockIdx.x * blockDim.x + threadIdx.x; e < E;
         e += gridDim.x * blockDim.x) {
        int d = __ldg(dst + e);
        int pos = atomicAdd(&g_cursor[d], 1);
        g_eid[pos] = e;
    }
}

// ---------------------------------------------------------------------------
// K4: per-node aggregation. One warp per node; lane owns 4 contiguous dims.
//     h[n] = (nfeat[n] + sum_{e in in(n)} (nfeat[src[e]] + efeat[e])) / (deg+1)
// ---------------------------------------------------------------------------
__global__ void aggregate_kernel(const float* __restrict__ nfeat,
                                 const int* __restrict__ src,
                                 const int* __restrict__ eidx,
                                 const float* __restrict__ emb,
                                 int N) {
    int n = blockIdx.x * (blockDim.x >> 5) + (threadIdx.x >> 5);
    if (n >= N) return;
    int lane = threadIdx.x & 31;

    const float4* nf4 = reinterpret_cast<const float4*>(nfeat);
    const float4* emb4 = reinterpret_cast<const float4*>(emb);

    int start = g_start[n];
    int end = g_start[n + 1];

    float4 acc = __ldg(nf4 + (size_t)n * 32 + lane);

    int i = start;
    // Unrolled-by-4 main loop for memory-level parallelism
    for (; i + 4 <= end; i += 4) {
        int e0 = g_eid[i + 0], e1 = g_eid[i + 1];
        int e2 = g_eid[i + 2], e3 = g_eid[i + 3];
        int s0 = __ldg(src + e0), s1 = __ldg(src + e1);
        int s2 = __ldg(src + e2), s3 = __ldg(src + e3);
        int a0 = __ldg(eidx + e0 * 3), b0 = __ldg(eidx + e0 * 3 + 1), c0 = __ldg(eidx + e0 * 3 + 2);
        int a1 = __ldg(eidx + e1 * 3), b1 = __ldg(eidx + e1 * 3 + 1), c1 = __ldg(eidx + e1 * 3 + 2);
        int a2 = __ldg(eidx + e2 * 3), b2 = __ldg(eidx + e2 * 3 + 1), c2 = __ldg(eidx + e2 * 3 + 2);
        int a3 = __ldg(eidx + e3 * 3), b3 = __ldg(eidx + e3 * 3 + 1), c3 = __ldg(eidx + e3 * 3 + 2);

        float4 v0 = __ldg(nf4 + (size_t)s0 * 32 + lane);
        float4 v1 = __ldg(nf4 + (size_t)s1 * 32 + lane);
        float4 v2 = __ldg(nf4 + (size_t)s2 * 32 + lane);
        float4 v3 = __ldg(nf4 + (size_t)s3 * 32 + lane);

        float4 p0 = f4add(f4add(__ldg(emb4 + a0 * 32 + lane), __ldg(emb4 + (8 + b0) * 32 + lane)),
                          __ldg(emb4 + (16 + c0) * 32 + lane));
        float4 p1 = f4add(f4add(__ldg(emb4 + a1 * 32 + lane), __ldg(emb4 + (8 + b1) * 32 + lane)),
                          __ldg(emb4 + (16 + c1) * 32 + lane));
        float4 p2 = f4add(f4add(__ldg(emb4 + a2 * 32 + lane), __ldg(emb4 + (8 + b2) * 32 + lane)),
                          __ldg(emb4 + (16 + c2) * 32 + lane));
        float4 p3 = f4add(f4add(__ldg(emb4 + a3 * 32 + lane), __ldg(emb4 + (8 + b3) * 32 + lane)),
                          __ldg(emb4 + (16 + c3) * 32 + lane));

        acc = f4add(acc, f4add(f4add(f4add(v0, p0), f4add(v1, p1)),
                               f4add(f4add(v2, p2), f4add(v3, p3))));
    }
    // Remainder
    for (; i < end; i++) {
        int e = g_eid[i];
        int s = __ldg(src + e);
        int a = __ldg(eidx + e * 3), b = __ldg(eidx + e * 3 + 1), c = __ldg(eidx + e * 3 + 2);
        float4 v = __ldg(nf4 + (size_t)s * 32 + lane);
        float4 p = f4add(f4add(__ldg(emb4 + a * 32 + lane), __ldg(emb4 + (8 + b) * 32 + lane)),
                         __ldg(emb4 + (16 + c) * 32 + lane));
        acc = f4add(acc, f4add(v, p));
    }

    float scale = 1.0f / (float)(end - start + 1);
    acc.x *= scale; acc.y *= scale; acc.z *= scale; acc.w *= scale;
    *reinterpret_cast<float4*>(g_h + (size_t)n * D_DIM + lane * 4) = acc;
}

// ---------------------------------------------------------------------------
// K5: out = g_h @ W + b  (unchanged GEMM: 64 rows x 128 cols per block)
// ---------------------------------------------------------------------------
#define HS 132  // h-tile row stride in floats (conflict-free for row-diff 1)

__global__ void gemm_kernel(const float* __restrict__ W,
                            const float* __restrict__ b,
                            float* __restrict__ out, int N) {
    extern __shared__ float sm[];
    float* Wsh = sm;                  // 128*128 floats
    float* hsh = sm + D_DIM * D_DIM;  // 64 * HS floats

    int tx = threadIdx.x;   // 0..15 (col groups of 8)
    int ty = threadIdx.y;   // 0..7  (row within group-of-8)
    int tid = ty * 16 + tx; // 0..127
    int row0 = blockIdx.x * 64;

    // Stage W into shared
    {
        const float4* W4 = reinterpret_cast<const float4*>(W);
        float4* Wsh4 = reinterpret_cast<float4*>(Wsh);
        #pragma unroll
        for (int i = tid; i < (D_DIM * D_DIM) / 4; i += 128)
            Wsh4[i] = __ldg(W4 + i);
    }

    // Stage h tile
    for (int i = tid; i < 64 * (D_DIM / 4); i += 128) {
        int lr = i >> 5;        // local row 0..63
        int cc = (i & 31) * 4;  // col 0..124 step 4
        int row = row0 + lr;
        float4 v = make_float4(0.f, 0.f, 0.f, 0.f);
        if (row < N)
            v = *reinterpret_cast<const float4*>(g_h + (size_t)row * D_DIM + cc);
        *reinterpret_cast<float4*>(hsh + lr * HS + cc) = v;
    }
    __syncthreads();

    float acc[8][8];
    #pragma unroll
    for (int r = 0; r < 8; r++)
        #pragma unroll
        for (int c = 0; c < 8; c++) acc[r][c] = 0.f;

    int colb = tx * 8;

    #pragma unroll 8
    for (int k = 0; k < D_DIM; k++) {
        float4 wa = *reinterpret_cast<const float4*>(Wsh + k * D_DIM + colb);
        float4 wb = *reinterpret_cast<const float4*>(Wsh + k * D_DIM + colb + 4);
        float hr[8];
        #pragma unroll
        for (int r = 0; r < 8; r++)
            hr[r] = hsh[(ty + r * 8) * HS + k];  // rows interleaved by 8
        #pragma unroll
        for (int r = 0; r < 8; r++) {
            acc[r][0] += hr[r] * wa.x;
            acc[r][1] += hr[r] * wa.y;
            acc[r][2] += hr[r] * wa.z;
            acc[r][3] += hr[r] * wa.w;
            acc[r][4] += hr[r] * wb.x;
            acc[r][5] += hr[r] * wb.y;
            acc[r][6] += hr[r] * wb.z;
            acc[r][7] += hr[r] * wb.w;
        }
    }

    float4 b0 = __ldg(reinterpret_cast<const float4*>(b + colb));
    float4 b1 = __ldg(reinterpret_cast<const float4*>(b + colb + 4));

    #pragma unroll
    for (int r = 0; r < 8; r++) {
        int row = row0 + ty + r * 8;
        if (row < N) {
            float4 o0 = make_float4(acc[r][0] + b0.x, acc[r][1] + b0.y,
                                    acc[r][2] + b0.z, acc[r][3] + b0.w);
            float4 o1 = make_float4(acc[r][4] + b1.x, acc[r][5] + b1.y,
                                    acc[r][6] + b1.z, acc[r][7] + b1.w);
            *reinterpret_cast<float4*>(out + (size_t)row * D_DIM + colb)     = o0;
            *reinterpret_cast<float4*>(out + (size_t)row * D_DIM + colb + 4) = o1;
        }
    }
}

// ---------------------------------------------------------------------------
// Launch
// Inputs (metadata order): nfeat[N*D] f32, src[E] i32, dst[E] i32,
//   efeat_idx[E*3] i32, edge_emb[3*8*128] f32, W[128*128] f32, b[128] f32
// Output: float[N*128]
// ---------------------------------------------------------------------------
extern "C" void kernel_launch(void* const* d_in, const int* in_sizes, int n_in,
                              void* d_out, int out_size) {
    const float* nfeat = (const float*)d_in[0];
    const int*   src   = (const int*)d_in[1];
    const int*   dst   = (const int*)d_in[2];
    const int*   eidx  = (const int*)d_in[3];
    const float* emb   = (const float*)d_in[4];
    const float* W     = (const float*)d_in[5];
    const float* b     = (const float*)d_in[6];
    float* out = (float*)d_out;

    int N = in_sizes[0] / D_DIM;
    int E = in_sizes[1];

    // K0: zero counters
    zero_cnt_kernel<<<(N + 511) / 512, 512>>>(N);

    // K1: in-degree histogram
    hist_kernel<<<592, 256>>>(dst, E);

    // K2: exclusive scan -> CSR starts + cursors
    scan_kernel<<<1, 1024>>>(N, E);

    // K3: fill CSR edge list
    fill_kernel<<<592, 256>>>(dst, E);

    // K4: per-node aggregate (+ normalize), 8 warps/block
    aggregate_kernel<<<(N + 7) / 8, 256>>>(nfeat, src, eidx, emb, N);

    // K5: GEMM + bias
    int smem = (D_DIM * D_DIM + 64 * HS) * (int)sizeof(float);  // 99328 B
    cudaFuncSetAttribute(gemm_kernel, cudaFuncAttributeMaxDynamicSharedMemorySize, smem);
    int gb = (N + 63) / 64;
    gemm_kernel<<<gb, dim3(16, 8), smem>>>(W, b, out, N);
}

// round 3
// speedup vs baseline: 1.6893x; 1.6893x over previous
#include <cuda_runtime.h>
#include <cuda_bf16.h>
#include <cstdint>

// Problem constants: N=50000, E=600000, D=128, NF=3, V=8
#define D_DIM 128
#define NF_DIM 3
#define V_DIM 8
#define MAX_N 50048

// Scratch (device globals; no allocation allowed)
__device__ float g_acc[MAX_N * D_DIM];   // neighbor message sums (zeroed each call)
__device__ float g_deg[MAX_N];           // in-degree (zeroed each call)

// ---------------------------------------------------------------------------
// K1: edge scatter. One warp per edge; lane owns 4 contiguous dims.
//     m = nfeat[src] + sum_f edge_emb[f, idx_f]  -> red.v4 onto g_acc[dst]
// ---------------------------------------------------------------------------
__global__ void edge_scatter_kernel(const float* __restrict__ nfeat,
                                    const int* __restrict__ src,
                                    const int* __restrict__ dst,
                                    const int* __restrict__ eidx,
                                    const float* __restrict__ emb,
                                    int E) {
    int e = blockIdx.x * (blockDim.x >> 5) + (threadIdx.x >> 5);
    if (e >= E) return;
    int lane = threadIdx.x & 31;

    int s  = __ldg(src + e);
    int d  = __ldg(dst + e);
    int i0 = __ldg(eidx + e * NF_DIM + 0);
    int i1 = __ldg(eidx + e * NF_DIM + 1);
    int i2 = __ldg(eidx + e * NF_DIM + 2);

    int c = lane * 4;
    float4 v  = __ldg(reinterpret_cast<const float4*>(nfeat + (size_t)s * D_DIM + c));
    float4 e0 = __ldg(reinterpret_cast<const float4*>(emb + ((0 * V_DIM + i0) * D_DIM) + c));
    float4 e1 = __ldg(reinterpret_cast<const float4*>(emb + ((1 * V_DIM + i1) * D_DIM) + c));
    float4 e2 = __ldg(reinterpret_cast<const float4*>(emb + ((2 * V_DIM + i2) * D_DIM) + c));

    float mx = v.x + e0.x + e1.x + e2.x;
    float my = v.y + e0.y + e1.y + e2.y;
    float mz = v.z + e0.z + e1.z + e2.z;
    float mw = v.w + e0.w + e1.w + e2.w;

    float* p = g_acc + (size_t)d * D_DIM + c;
    asm volatile("red.global.add.v4.f32 [%0], {%1, %2, %3, %4};"
                 :: "l"(p), "f"(mx), "f"(my), "f"(mz), "f"(mw) : "memory");

    if (lane == 0) {
        atomicAdd(&g_deg[d], 1.0f);  // no return use -> REDG
    }
}

// ---------------------------------------------------------------------------
// K2: out = ((nfeat + g_acc) / (g_deg + 1)) @ W + b  via tf32 mma (3xTF32)
//     Block: 256 threads = 8 warps, tile 128 rows x 128 cols.
//     Warp tile: 64 rows x 32 cols (warp grid 2x4).
//     Smem: Wh[128][136], Wl[128][136] (pre-split hi/lo), H[128][132], bias.
// ---------------------------------------------------------------------------
#define WS 136  // W smem stride (conflict-free B-fragment loads)
#define HSTR 132  // H smem stride (conflict-free A-fragment loads)

__device__ __forceinline__ uint32_t f2tf32(float x) {
    uint32_t r;
    asm("cvt.rna.tf32.f32 %0, %1;" : "=r"(r) : "f"(x));
    return r;
}

__global__ void __launch_bounds__(256, 1)
gemm_tf32_kernel(const float* __restrict__ nfeat,
                 const float* __restrict__ W,
                 const float* __restrict__ b,
                 float* __restrict__ out, int N) {
    extern __shared__ float sm[];
    float* Whs = sm;                         // 128*136
    float* Wls = Whs + D_DIM * WS;           // 128*136
    float* Hs  = Wls + D_DIM * WS;           // 128*132
    float* bs  = Hs + D_DIM * HSTR;          // 128

    int tid = threadIdx.x;
    int row0 = blockIdx.x * 128;

    // Stage W split hi/lo
    {
        const float4* W4 = reinterpret_cast<const float4*>(W);
        for (int i = tid; i < (D_DIM * D_DIM) / 4; i += 256) {
            float4 w = __ldg(W4 + i);
            int k = i >> 5;
            int n = (i & 31) * 4;
            uint32_t h0 = f2tf32(w.x), h1 = f2tf32(w.y), h2 = f2tf32(w.z), h3 = f2tf32(w.w);
            float l0 = w.x - __uint_as_float(h0);
            float l1 = w.y - __uint_as_float(h1);
            float l2 = w.z - __uint_as_float(h2);
            float l3 = w.w - __uint_as_float(h3);
            float4 hv = make_float4(__uint_as_float(h0), __uint_as_float(h1),
                                    __uint_as_float(h2), __uint_as_float(h3));
            float4 lv = make_float4(__uint_as_float(f2tf32(l0)), __uint_as_float(f2tf32(l1)),
                                    __uint_as_float(f2tf32(l2)), __uint_as_float(f2tf32(l3)));
            *reinterpret_cast<float4*>(Whs + k * WS + n) = hv;
            *reinterpret_cast<float4*>(Wls + k * WS + n) = lv;
        }
        if (tid < D_DIM) bs[tid] = __ldg(b + tid);
    }

    // Stage H tile: h = (nfeat + acc) / (deg + 1)
    {
        const float4* nf4 = reinterpret_cast<const float4*>(nfeat);
        const float4* ac4 = reinterpret_cast<const float4*>(g_acc);
        for (int i = tid; i < 128 * 32; i += 256) {
            int lr = i >> 5;
            int c4 = (i & 31) * 4;
            int row = row0 + lr;
            float4 v = make_float4(0.f, 0.f, 0.f, 0.f);
            if (row < N) {
                float4 nv = __ldg(nf4 + (size_t)row * 32 + (c4 >> 2));
                float4 av = *(ac4 + (size_t)row * 32 + (c4 >> 2));
                float invd = 1.0f / (g_deg[row] + 1.0f);
                v = make_float4((nv.x + av.x) * invd, (nv.y + av.y) * invd,
                                (nv.z + av.z) * invd, (nv.w + av.w) * invd);
            }
            *reinterpret_cast<float4*>(Hs + lr * HSTR + c4) = v;
        }
    }
    __syncthreads();

    int wid = tid >> 5;
    int lane = tid & 31;
    int gid = lane >> 2;   // group id 0..7
    int tig = lane & 3;    // thread in group 0..3
    int wr = (wid >> 2) * 64;   // warp row base within tile (0 or 64)
    int wc = (wid & 3) * 32;    // warp col base (0,32,64,96)

    float c[4][4][4];  // [m-tile][n-tile][reg]
    #pragma unroll
    for (int mt = 0; mt < 4; mt++)
        #pragma unroll
        for (int nt = 0; nt < 4; nt++)
            #pragma unroll
            for (int r = 0; r < 4; r++) c[mt][nt][r] = 0.f;

    #pragma unroll 1
    for (int k0 = 0; k0 < D_DIM; k0 += 8) {
        // A fragments (hi + lo), 4 m-tiles
        uint32_t ah[4][4], al[4][4];
        #pragma unroll
        for (int mt = 0; mt < 4; mt++) {
            int r_lo = wr + mt * 16 + gid;
            float a0 = Hs[r_lo * HSTR + k0 + tig];
            float a1 = Hs[(r_lo + 8) * HSTR + k0 + tig];
            float a2 = Hs[r_lo * HSTR + k0 + tig + 4];
            float a3 = Hs[(r_lo + 8) * HSTR + k0 + tig + 4];
            ah[mt][0] = f2tf32(a0); al[mt][0] = f2tf32(a0 - __uint_as_float(ah[mt][0]));
            ah[mt][1] = f2tf32(a1); al[mt][1] = f2tf32(a1 - __uint_as_float(ah[mt][1]));
            ah[mt][2] = f2tf32(a2); al[mt][2] = f2tf32(a2 - __uint_as_float(ah[mt][2]));
            ah[mt][3] = f2tf32(a3); al[mt][3] = f2tf32(a3 - __uint_as_float(ah[mt][3]));
        }
        // B fragments (hi + lo), 4 n-tiles
        uint32_t bh[4][2], bl[4][2];
        #pragma unroll
        for (int nt = 0; nt < 4; nt++) {
            int col = wc + nt * 8 + gid;
            bh[nt][0] = __float_as_uint(Whs[(k0 + tig) * WS + col]);
            bh[nt][1] = __float_as_uint(Whs[(k0 + tig + 4) * WS + col]);
            bl[nt][0] = __float_as_uint(Wls[(k0 + tig) * WS + col]);
            bl[nt][1] = __float_as_uint(Wls[(k0 + tig + 4) * WS + col]);
        }
        #pragma unroll
        for (int mt = 0; mt < 4; mt++) {
            #pragma unroll
            for (int nt = 0; nt < 4; nt++) {
                #define MMA(A, B)                                                        \
                    asm volatile(                                                        \
                        "mma.sync.aligned.m16n8k8.row.col.f32.tf32.tf32.f32 "            \
                        "{%0,%1,%2,%3}, {%4,%5,%6,%7}, {%8,%9}, {%0,%1,%2,%3};"          \
                        : "+f"(c[mt][nt][0]), "+f"(c[mt][nt][1]),                        \
                          "+f"(c[mt][nt][2]), "+f"(c[mt][nt][3])                         \
                        : "r"(A[0]), "r"(A[1]), "r"(A[2]), "r"(A[3]),                    \
                          "r"(B[0]), "r"(B[1]))
                MMA(ah[mt], bh[nt]);
                MMA(al[mt], bh[nt]);
                MMA(ah[mt], bl[nt]);
                #undef MMA
            }
        }
    }

    // Epilogue: add bias, store
    #pragma unroll
    for (int mt = 0; mt < 4; mt++) {
        #pragma unroll
        for (int nt = 0; nt < 4; nt++) {
            int col = wc + nt * 8 + 2 * tig;
            float bx = bs[col], by = bs[col + 1];
            int r_top = row0 + wr + mt * 16 + gid;
            if (r_top < N) {
                float2 o = make_float2(c[mt][nt][0] + bx, c[mt][nt][1] + by);
                *reinterpret_cast<float2*>(out + (size_t)r_top * D_DIM + col) = o;
            }
            int r_bot = r_top + 8;
            if (r_bot < N) {
                float2 o = make_float2(c[mt][nt][2] + bx, c[mt][nt][3] + by);
                *reinterpret_cast<float2*>(out + (size_t)r_bot * D_DIM + col) = o;
            }
        }
    }
}

// ---------------------------------------------------------------------------
// Launch
// Inputs: nfeat[N*D] f32, src[E] i32, dst[E] i32, efeat_idx[E*3] i32,
//         edge_emb[3*8*128] f32, W[128*128] f32, b[128] f32  -> out float[N*128]
// ---------------------------------------------------------------------------
extern "C" void kernel_launch(void* const* d_in, const int* in_sizes, int n_in,
                              void* d_out, int out_size) {
    const float* nfeat = (const float*)d_in[0];
    const int*   src   = (const int*)d_in[1];
    const int*   dst   = (const int*)d_in[2];
    const int*   eidx  = (const int*)d_in[3];
    const float* emb   = (const float*)d_in[4];
    const float* W     = (const float*)d_in[5];
    const float* b     = (const float*)d_in[6];
    float* out = (float*)d_out;

    int N = in_sizes[0] / D_DIM;
    int E = in_sizes[1];

    // Zero accumulators (graph-capturable async memsets; no allocation)
    void* acc_ptr = nullptr;
    void* deg_ptr = nullptr;
    cudaGetSymbolAddress(&acc_ptr, g_acc);
    cudaGetSymbolAddress(&deg_ptr, g_deg);
    cudaMemsetAsync(acc_ptr, 0, (size_t)N * D_DIM * sizeof(float));
    cudaMemsetAsync(deg_ptr, 0, (size_t)N * sizeof(float));

    // Edge scatter: 8 edges per 256-thread block
    edge_scatter_kernel<<<(E + 7) / 8, 256>>>(nfeat, src, dst, eidx, emb, E);

    // GEMM (tf32 tensor cores, 3xTF32 compensation)
    int smem = (2 * D_DIM * WS + D_DIM * HSTR + 128) * (int)sizeof(float);
    cudaFuncSetAttribute(gemm_tf32_kernel, cudaFuncAttributeMaxDynamicSharedMemorySize, smem);
    int gb = (N + 127) / 128;
    gemm_tf32_kernel<<<gb, 256, smem>>>(nfeat, W, b, out, N);
}

// round 4
// speedup vs baseline: 1.7243x; 1.0207x over previous
#include <cuda_runtime.h>
#include <cuda_bf16.h>
#include <cstdint>

// Problem constants: N=50000, E=600000, D=128, NF=3, V=8
#define D_DIM 128
#define NF_DIM 3
#define V_DIM 8
#define MAX_N 50048

// Scratch (device globals; no allocation allowed)
__device__ float g_acc[MAX_N * D_DIM];   // neighbor message sums (zeroed each call)
__device__ float g_deg[MAX_N];           // in-degree (zeroed each call)
__device__ float g_Wh[D_DIM * D_DIM];    // W tf32-hi (bit pattern in fp32)
__device__ float g_Wl[D_DIM * D_DIM];    // W tf32-lo

__device__ __forceinline__ uint32_t f2tf32(float x) {
    uint32_t r;
    asm("cvt.rna.tf32.f32 %0, %1;" : "=r"(r) : "f"(x));
    return r;
}

// ---------------------------------------------------------------------------
// K0: split W into tf32 hi/lo ONCE (not per GEMM block)
// ---------------------------------------------------------------------------
__global__ void wsplit_kernel(const float* __restrict__ W) {
    int i = blockIdx.x * blockDim.x + threadIdx.x;  // float4 index
    if (i >= (D_DIM * D_DIM) / 4) return;
    float4 w = __ldg(reinterpret_cast<const float4*>(W) + i);
    uint32_t h0 = f2tf32(w.x), h1 = f2tf32(w.y), h2 = f2tf32(w.z), h3 = f2tf32(w.w);
    float4 hv = make_float4(__uint_as_float(h0), __uint_as_float(h1),
                            __uint_as_float(h2), __uint_as_float(h3));
    float4 lv = make_float4(
        __uint_as_float(f2tf32(w.x - hv.x)), __uint_as_float(f2tf32(w.y - hv.y)),
        __uint_as_float(f2tf32(w.z - hv.z)), __uint_as_float(f2tf32(w.w - hv.w)));
    reinterpret_cast<float4*>(g_Wh)[i] = hv;
    reinterpret_cast<float4*>(g_Wl)[i] = lv;
}

// ---------------------------------------------------------------------------
// K1: edge scatter. One warp per edge; lane owns 4 contiguous dims.
// ---------------------------------------------------------------------------
__global__ void edge_scatter_kernel(const float* __restrict__ nfeat,
                                    const int* __restrict__ src,
                                    const int* __restrict__ dst,
                                    const int* __restrict__ eidx,
                                    const float* __restrict__ emb,
                                    int E) {
    int e = blockIdx.x * (blockDim.x >> 5) + (threadIdx.x >> 5);
    if (e >= E) return;
    int lane = threadIdx.x & 31;

    int s  = __ldg(src + e);
    int d  = __ldg(dst + e);
    int i0 = __ldg(eidx + e * NF_DIM + 0);
    int i1 = __ldg(eidx + e * NF_DIM + 1);
    int i2 = __ldg(eidx + e * NF_DIM + 2);

    int c = lane * 4;
    float4 v  = __ldg(reinterpret_cast<const float4*>(nfeat + (size_t)s * D_DIM + c));
    float4 e0 = __ldg(reinterpret_cast<const float4*>(emb + ((0 * V_DIM + i0) * D_DIM) + c));
    float4 e1 = __ldg(reinterpret_cast<const float4*>(emb + ((1 * V_DIM + i1) * D_DIM) + c));
    float4 e2 = __ldg(reinterpret_cast<const float4*>(emb + ((2 * V_DIM + i2) * D_DIM) + c));

    float mx = v.x + e0.x + e1.x + e2.x;
    float my = v.y + e0.y + e1.y + e2.y;
    float mz = v.z + e0.z + e1.z + e2.z;
    float mw = v.w + e0.w + e1.w + e2.w;

    float* p = g_acc + (size_t)d * D_DIM + c;
    asm volatile("red.global.add.v4.f32 [%0], {%1, %2, %3, %4};"
                 :: "l"(p), "f"(mx), "f"(my), "f"(mz), "f"(mw) : "memory");

    if (lane == 0) {
        atomicAdd(&g_deg[d], 1.0f);
    }
}

// ---------------------------------------------------------------------------
// K2: PERSISTENT GEMM. grid=148 blocks x 256 threads. Each block stages
//     pre-split W once, then loops over 128-row tiles.
//     out = ((nfeat + g_acc) / (g_deg + 1)) @ W + b   (3xTF32 mma)
// ---------------------------------------------------------------------------
#define WS 136    // W smem stride (conflict-free B-fragment loads)
#define HSTR 132  // H smem stride (conflict-free A-fragment loads)

__global__ void __launch_bounds__(256, 1)
gemm_persist_kernel(const float* __restrict__ nfeat,
                    const float* __restrict__ b,
                    float* __restrict__ out, int N, int numTiles) {
    extern __shared__ float sm[];
    float* Whs = sm;                         // 128*136
    float* Wls = Whs + D_DIM * WS;           // 128*136
    float* Hs  = Wls + D_DIM * WS;           // 128*132
    float* bs  = Hs + D_DIM * HSTR;          // 128

    int tid = threadIdx.x;

    // Stage W (pure copies of pre-split tf32 hi/lo)
    {
        const float4* Wh4 = reinterpret_cast<const float4*>(g_Wh);
        const float4* Wl4 = reinterpret_cast<const float4*>(g_Wl);
        #pragma unroll
        for (int i = tid; i < (D_DIM * D_DIM) / 4; i += 256) {
            int k = i >> 5;
            int n = (i & 31) * 4;
            *reinterpret_cast<float4*>(Whs + k * WS + n) = Wh4[i];
            *reinterpret_cast<float4*>(Wls + k * WS + n) = Wl4[i];
        }
        if (tid < D_DIM) bs[tid] = __ldg(b + tid);
    }

    int wid = tid >> 5;
    int lane = tid & 31;
    int gid = lane >> 2;        // group id 0..7
    int tig = lane & 3;         // thread in group 0..3
    int wr = (wid >> 2) * 64;   // warp row base (0 or 64)
    int wc = (wid & 3) * 32;    // warp col base (0,32,64,96)

    const float4* nf4 = reinterpret_cast<const float4*>(nfeat);
    const float4* ac4 = reinterpret_cast<const float4*>(g_acc);

    for (int tile = blockIdx.x; tile < numTiles; tile += gridDim.x) {
        int row0 = tile * 128;

        __syncthreads();  // previous iteration's compute done before Hs overwrite

        // Stage H tile: h = (nfeat + acc) / (deg + 1)
        for (int i = tid; i < 128 * 32; i += 256) {
            int lr = i >> 5;
            int c4 = i & 31;
            int row = row0 + lr;
            float4 v = make_float4(0.f, 0.f, 0.f, 0.f);
            if (row < N) {
                float4 nv = __ldg(nf4 + (size_t)row * 32 + c4);
                float4 av = *(ac4 + (size_t)row * 32 + c4);
                float invd = 1.0f / (g_deg[row] + 1.0f);
                v = make_float4((nv.x + av.x) * invd, (nv.y + av.y) * invd,
                                (nv.z + av.z) * invd, (nv.w + av.w) * invd);
            }
            *reinterpret_cast<float4*>(Hs + lr * HSTR + c4 * 4) = v;
        }
        __syncthreads();

        float c[4][4][4];
        #pragma unroll
        for (int mt = 0; mt < 4; mt++)
            #pragma unroll
            for (int nt = 0; nt < 4; nt++)
                #pragma unroll
                for (int r = 0; r < 4; r++) c[mt][nt][r] = 0.f;

        #pragma unroll 1
        for (int k0 = 0; k0 < D_DIM; k0 += 8) {
            uint32_t ah[4][4], al[4][4];
            #pragma unroll
            for (int mt = 0; mt < 4; mt++) {
                int r_lo = wr + mt * 16 + gid;
                float a0 = Hs[r_lo * HSTR + k0 + tig];
                float a1 = Hs[(r_lo + 8) * HSTR + k0 + tig];
                float a2 = Hs[r_lo * HSTR + k0 + tig + 4];
                float a3 = Hs[(r_lo + 8) * HSTR + k0 + tig + 4];
                ah[mt][0] = f2tf32(a0); al[mt][0] = f2tf32(a0 - __uint_as_float(ah[mt][0]));
                ah[mt][1] = f2tf32(a1); al[mt][1] = f2tf32(a1 - __uint_as_float(ah[mt][1]));
                ah[mt][2] = f2tf32(a2); al[mt][2] = f2tf32(a2 - __uint_as_float(ah[mt][2]));
                ah[mt][3] = f2tf32(a3); al[mt][3] = f2tf32(a3 - __uint_as_float(ah[mt][3]));
            }
            uint32_t bh[4][2], bl[4][2];
            #pragma unroll
            for (int nt = 0; nt < 4; nt++) {
                int col = wc + nt * 8 + gid;
                bh[nt][0] = __float_as_uint(Whs[(k0 + tig) * WS + col]);
                bh[nt][1] = __float_as_uint(Whs[(k0 + tig + 4) * WS + col]);
                bl[nt][0] = __float_as_uint(Wls[(k0 + tig) * WS + col]);
                bl[nt][1] = __float_as_uint(Wls[(k0 + tig + 4) * WS + col]);
            }
            #pragma unroll
            for (int mt = 0; mt < 4; mt++) {
                #pragma unroll
                for (int nt = 0; nt < 4; nt++) {
                    #define MMA(A, B)                                                    \
                        asm volatile(                                                    \
                            "mma.sync.aligned.m16n8k8.row.col.f32.tf32.tf32.f32 "        \
                            "{%0,%1,%2,%3}, {%4,%5,%6,%7}, {%8,%9}, {%0,%1,%2,%3};"      \
                            : "+f"(c[mt][nt][0]), "+f"(c[mt][nt][1]),                    \
                              "+f"(c[mt][nt][2]), "+f"(c[mt][nt][3])                     \
                            : "r"(A[0]), "r"(A[1]), "r"(A[2]), "r"(A[3]),                \
                              "r"(B[0]), "r"(B[1]))
                    MMA(ah[mt], bh[nt]);
                    MMA(al[mt], bh[nt]);
                    MMA(ah[mt], bl[nt]);
                    #undef MMA
                }
            }
        }

        // Epilogue
        #pragma unroll
        for (int mt = 0; mt < 4; mt++) {
            #pragma unroll
            for (int nt = 0; nt < 4; nt++) {
                int col = wc + nt * 8 + 2 * tig;
                float bx = bs[col], by = bs[col + 1];
                int r_top = row0 + wr + mt * 16 + gid;
                if (r_top < N) {
                    float2 o = make_float2(c[mt][nt][0] + bx, c[mt][nt][1] + by);
                    *reinterpret_cast<float2*>(out + (size_t)r_top * D_DIM + col) = o;
                }
                int r_bot = r_top + 8;
                if (r_bot < N) {
                    float2 o = make_float2(c[mt][nt][2] + bx, c[mt][nt][3] + by);
                    *reinterpret_cast<float2*>(out + (size_t)r_bot * D_DIM + col) = o;
                }
            }
        }
    }
}

// ---------------------------------------------------------------------------
// Launch
// Inputs: nfeat[N*D] f32, src[E] i32, dst[E] i32, efeat_idx[E*3] i32,
//         edge_emb[3*8*128] f32, W[128*128] f32, b[128] f32 -> out float[N*128]
// ---------------------------------------------------------------------------
extern "C" void kernel_launch(void* const* d_in, const int* in_sizes, int n_in,
                              void* d_out, int out_size) {
    const float* nfeat = (const float*)d_in[0];
    const int*   src   = (const int*)d_in[1];
    const int*   dst   = (const int*)d_in[2];
    const int*   eidx  = (const int*)d_in[3];
    const float* emb   = (const float*)d_in[4];
    const float* W     = (const float*)d_in[5];
    const float* b     = (const float*)d_in[6];
    float* out = (float*)d_out;

    int N = in_sizes[0] / D_DIM;
    int E = in_sizes[1];

    // Zero accumulators (graph-capturable async memsets)
    void* acc_ptr = nullptr;
    void* deg_ptr = nullptr;
    cudaGetSymbolAddress(&acc_ptr, g_acc);
    cudaGetSymbolAddress(&deg_ptr, g_deg);
    cudaMemsetAsync(acc_ptr, 0, (size_t)N * D_DIM * sizeof(float));
    cudaMemsetAsync(deg_ptr, 0, (size_t)N * sizeof(float));

    // Split W once
    wsplit_kernel<<<16, 256>>>(W);

    // Edge scatter: 8 edges per 256-thread block
    edge_scatter_kernel<<<(E + 7) / 8, 256>>>(nfeat, src, dst, eidx, emb, E);

    // Persistent GEMM
    int numTiles = (N + 127) / 128;
    int smem = (2 * D_DIM * WS + D_DIM * HSTR + 128) * (int)sizeof(float);
    cudaFuncSetAttribute(gemm_persist_kernel, cudaFuncAttributeMaxDynamicSharedMemorySize, smem);
    gemm_persist_kernel<<<148, 256, smem>>>(nfeat, b, out, N, numTiles);
}

// round 5
// speedup vs baseline: 2.0040x; 1.1622x over previous
#include <cuda_runtime.h>
#include <cuda_bf16.h>
#include <cstdint>

// Problem constants: N=50000, E=600000, D=128, NF=3, V=8
#define D_DIM 128
#define NF_DIM 3
#define V_DIM 8
#define MAX_N 50048

// Scratch (device globals; no allocation allowed)
__device__ float g_acc[MAX_N * D_DIM];   // neighbor message sums (zeroed each call)
__device__ float g_deg[MAX_N];           // in-degree (zeroed each call)

// ---------------------------------------------------------------------------
// K1: edge scatter. One warp per edge; lane owns 4 contiguous dims.
// ---------------------------------------------------------------------------
__global__ void edge_scatter_kernel(const float* __restrict__ nfeat,
                                    const int* __restrict__ src,
                                    const int* __restrict__ dst,
                                    const int* __restrict__ eidx,
                                    const float* __restrict__ emb,
                                    int E) {
    int e = blockIdx.x * (blockDim.x >> 5) + (threadIdx.x >> 5);
    if (e >= E) return;
    int lane = threadIdx.x & 31;

    int s  = __ldg(src + e);
    int d  = __ldg(dst + e);
    int i0 = __ldg(eidx + e * NF_DIM + 0);
    int i1 = __ldg(eidx + e * NF_DIM + 1);
    int i2 = __ldg(eidx + e * NF_DIM + 2);

    int c = lane * 4;
    float4 v  = __ldg(reinterpret_cast<const float4*>(nfeat + (size_t)s * D_DIM + c));
    float4 e0 = __ldg(reinterpret_cast<const float4*>(emb + ((0 * V_DIM + i0) * D_DIM) + c));
    float4 e1 = __ldg(reinterpret_cast<const float4*>(emb + ((1 * V_DIM + i1) * D_DIM) + c));
    float4 e2 = __ldg(reinterpret_cast<const float4*>(emb + ((2 * V_DIM + i2) * D_DIM) + c));

    float mx = v.x + e0.x + e1.x + e2.x;
    float my = v.y + e0.y + e1.y + e2.y;
    float mz = v.z + e0.z + e1.z + e2.z;
    float mw = v.w + e0.w + e1.w + e2.w;

    float* p = g_acc + (size_t)d * D_DIM + c;
    asm volatile("red.global.add.v4.f32 [%0], {%1, %2, %3, %4};"
                 :: "l"(p), "f"(mx), "f"(my), "f"(mz), "f"(mw) : "memory");

    if (lane == 0) {
        atomicAdd(&g_deg[d], 1.0f);
    }
}

// ---------------------------------------------------------------------------
// K2: PERSISTENT bf16x3 GEMM. grid=148 x 512 threads (16 warps).
//     out = ((nfeat + g_acc) / (g_deg + 1)) @ W + b
//     Smem (all pre-split bf16, packed (k,k+1) pairs in 32-bit words):
//       Wth[n][k], Wtl[n][k]  (W transposed: B frags need k-adjacent pairs)
//       Hh[m][k],  Hl[m][k]
//     Row stride 68 words (136 bf16) -> fragment loads bank-conflict-free.
// ---------------------------------------------------------------------------
#define SBW 68  // 32-bit words per smem row

__device__ __forceinline__ uint32_t pack_bf2(float a, float b) {
    __nv_bfloat162 h = __floats2bfloat162_rn(a, b);
    return *reinterpret_cast<uint32_t*>(&h);
}

__global__ void __launch_bounds__(512, 1)
gemm_bf16_kernel(const float* __restrict__ nfeat,
                 const float* __restrict__ W,
                 const float* __restrict__ b,
                 float* __restrict__ out, int N, int numTiles) {
    extern __shared__ uint32_t smu[];
    uint32_t* Wth = smu;                 // 128*68 words
    uint32_t* Wtl = Wth + D_DIM * SBW;
    uint32_t* Hh  = Wtl + D_DIM * SBW;
    uint32_t* Hl  = Hh + D_DIM * SBW;
    float* bs = reinterpret_cast<float*>(Hl + D_DIM * SBW);  // 128 floats

    int tid = threadIdx.x;

    // Stage W transposed, split into bf16 hi/lo (once per persistent block)
    {
        __nv_bfloat16* Wth_b = reinterpret_cast<__nv_bfloat16*>(Wth);
        __nv_bfloat16* Wtl_b = reinterpret_cast<__nv_bfloat16*>(Wtl);
        const float4* W4 = reinterpret_cast<const float4*>(W);
        for (int i = tid; i < (D_DIM * D_DIM) / 4; i += 512) {
            int k = i >> 5;
            int n4 = (i & 31) * 4;
            float4 w = __ldg(W4 + i);
            #pragma unroll
            for (int j = 0; j < 4; j++) {
                float x = (&w.x)[j];
                __nv_bfloat16 hb = __float2bfloat16_rn(x);
                __nv_bfloat16 lb = __float2bfloat16_rn(x - __bfloat162float(hb));
                Wth_b[(n4 + j) * (2 * SBW) + k] = hb;
                Wtl_b[(n4 + j) * (2 * SBW) + k] = lb;
            }
        }
        if (tid < D_DIM) bs[tid] = __ldg(b + tid);
    }

    int wid = tid >> 5;
    int lane = tid & 31;
    int gid = lane >> 2;        // 0..7
    int tig = lane & 3;         // 0..3
    int wr = (wid >> 2) * 32;   // warp row base 0/32/64/96
    int wc = (wid & 3) * 32;    // warp col base 0/32/64/96

    const float4* nf4 = reinterpret_cast<const float4*>(nfeat);
    const float4* ac4 = reinterpret_cast<const float4*>(g_acc);

    for (int tile = blockIdx.x; tile < numTiles; tile += gridDim.x) {
        int row0 = tile * 128;

        __syncthreads();  // previous tile's MMA reads done before Hh/Hl overwrite

        // Stage H: h = (nfeat + acc) / (deg + 1), split bf16 hi/lo
        for (int i = tid; i < 128 * 32; i += 512) {
            int lr = i >> 5;
            int c4 = i & 31;            // float4 index -> k = 4*c4
            int row = row0 + lr;
            float4 v = make_float4(0.f, 0.f, 0.f, 0.f);
            if (row < N) {
                float4 nv = __ldg(nf4 + (size_t)row * 32 + c4);
                float4 av = *(ac4 + (size_t)row * 32 + c4);
                float invd = 1.0f / (g_deg[row] + 1.0f);
                v = make_float4((nv.x + av.x) * invd, (nv.y + av.y) * invd,
                                (nv.z + av.z) * invd, (nv.w + av.w) * invd);
            }
            __nv_bfloat16 hx = __float2bfloat16_rn(v.x);
            __nv_bfloat16 hy = __float2bfloat16_rn(v.y);
            __nv_bfloat16 hz = __float2bfloat16_rn(v.z);
            __nv_bfloat16 hw = __float2bfloat16_rn(v.w);
            int base = lr * SBW + c4 * 2;
            Hh[base]     = pack_bf2(__bfloat162float(hx), __bfloat162float(hy));
            Hh[base + 1] = pack_bf2(__bfloat162float(hz), __bfloat162float(hw));
            Hl[base]     = pack_bf2(v.x - __bfloat162float(hx), v.y - __bfloat162float(hy));
            Hl[base + 1] = pack_bf2(v.z - __bfloat162float(hz), v.w - __bfloat162float(hw));
        }
        __syncthreads();

        float c[2][4][4];
        #pragma unroll
        for (int mt = 0; mt < 2; mt++)
            #pragma unroll
            for (int nt = 0; nt < 4; nt++)
                #pragma unroll
                for (int r = 0; r < 4; r++) c[mt][nt][r] = 0.f;

        #pragma unroll
        for (int kw = 0; kw < 64; kw += 8) {   // kw = k/2 (word index); K chunk = 16
            uint32_t ah[2][4], al[2][4];
            #pragma unroll
            for (int mt = 0; mt < 2; mt++) {
                int r = wr + mt * 16 + gid;
                ah[mt][0] = Hh[r * SBW + kw + tig];
                ah[mt][1] = Hh[(r + 8) * SBW + kw + tig];
                ah[mt][2] = Hh[r * SBW + kw + 4 + tig];
                ah[mt][3] = Hh[(r + 8) * SBW + kw + 4 + tig];
                al[mt][0] = Hl[r * SBW + kw + tig];
                al[mt][1] = Hl[(r + 8) * SBW + kw + tig];
                al[mt][2] = Hl[r * SBW + kw + 4 + tig];
                al[mt][3] = Hl[(r + 8) * SBW + kw + 4 + tig];
            }
            uint32_t bh[4][2], bl[4][2];
            #pragma unroll
            for (int nt = 0; nt < 4; nt++) {
                int n = wc + nt * 8 + gid;
                bh[nt][0] = Wth[n * SBW + kw + tig];
                bh[nt][1] = Wth[n * SBW + kw + 4 + tig];
                bl[nt][0] = Wtl[n * SBW + kw + tig];
                bl[nt][1] = Wtl[n * SBW + kw + 4 + tig];
            }
            #pragma unroll
            for (int mt = 0; mt < 2; mt++) {
                #pragma unroll
                for (int nt = 0; nt < 4; nt++) {
                    #define MMA16(A, B)                                                  \
                        asm volatile(                                                    \
                            "mma.sync.aligned.m16n8k16.row.col.f32.bf16.bf16.f32 "       \
                            "{%0,%1,%2,%3}, {%4,%5,%6,%7}, {%8,%9}, {%0,%1,%2,%3};"      \
                            : "+f"(c[mt][nt][0]), "+f"(c[mt][nt][1]),                    \
                              "+f"(c[mt][nt][2]), "+f"(c[mt][nt][3])                     \
                            : "r"(A[0]), "r"(A[1]), "r"(A[2]), "r"(A[3]),                \
                              "r"(B[0]), "r"(B[1]))
                    MMA16(ah[mt], bh[nt]);
                    MMA16(al[mt], bh[nt]);
                    MMA16(ah[mt], bl[nt]);
                    #undef MMA16
                }
            }
        }

        // Epilogue: add bias, store
        #pragma unroll
        for (int mt = 0; mt < 2; mt++) {
            #pragma unroll
            for (int nt = 0; nt < 4; nt++) {
                int col = wc + nt * 8 + 2 * tig;
                float bx = bs[col], by = bs[col + 1];
                int r_top = row0 + wr + mt * 16 + gid;
                if (r_top < N) {
                    float2 o = make_float2(c[mt][nt][0] + bx, c[mt][nt][1] + by);
                    *reinterpret_cast<float2*>(out + (size_t)r_top * D_DIM + col) = o;
                }
                int r_bot = r_top + 8;
                if (r_bot < N) {
                    float2 o = make_float2(c[mt][nt][2] + bx, c[mt][nt][3] + by);
                    *reinterpret_cast<float2*>(out + (size_t)r_bot * D_DIM + col) = o;
                }
            }
        }
    }
}

// ---------------------------------------------------------------------------
// Launch
// Inputs: nfeat[N*D] f32, src[E] i32, dst[E] i32, efeat_idx[E*3] i32,
//         edge_emb[3*8*128] f32, W[128*128] f32, b[128] f32 -> out float[N*128]
// ---------------------------------------------------------------------------
extern "C" void kernel_launch(void* const* d_in, const int* in_sizes, int n_in,
                              void* d_out, int out_size) {
    const float* nfeat = (const float*)d_in[0];
    const int*   src   = (const int*)d_in[1];
    const int*   dst   = (const int*)d_in[2];
    const int*   eidx  = (const int*)d_in[3];
    const float* emb   = (const float*)d_in[4];
    const float* W     = (const float*)d_in[5];
    const float* b     = (const float*)d_in[6];
    float* out = (float*)d_out;

    int N = in_sizes[0] / D_DIM;
    int E = in_sizes[1];

    // Zero accumulators (graph-capturable async memsets)
    void* acc_ptr = nullptr;
    void* deg_ptr = nullptr;
    cudaGetSymbolAddress(&acc_ptr, g_acc);
    cudaGetSymbolAddress(&deg_ptr, g_deg);
    cudaMemsetAsync(acc_ptr, 0, (size_t)N * D_DIM * sizeof(float));
    cudaMemsetAsync(deg_ptr, 0, (size_t)N * sizeof(float));

    // Edge scatter: 8 edges per 256-thread block
    edge_scatter_kernel<<<(E + 7) / 8, 256>>>(nfeat, src, dst, eidx, emb, E);

    // Persistent bf16x3 GEMM
    int numTiles = (N + 127) / 128;
    int smem = (4 * D_DIM * SBW) * 4 + 128 * 4;  // 139264 + 512 bytes
    cudaFuncSetAttribute(gemm_bf16_kernel, cudaFuncAttributeMaxDynamicSharedMemorySize, smem);
    gemm_bf16_kernel<<<148, 512, smem>>>(nfeat, W, b, out, N, numTiles);
}